// round 16
// baseline (speedup 1.0000x reference)
#include <cuda_runtime.h>
#include <cuda_fp16.h>
#include <math.h>
#include <stdint.h>
#include <limits.h>

// Problem constants
#define BB   4
#define SS   4096
#define DD   1024
#define HH   16
#define MR   (BB*SS)          // 16384 rows
#define SEG  128
#define NSEG (SS/SEG)         // 32

#define NST  3                // pipeline stages
#define STB  32768            // bytes per stage (A 16KB + B 16KB)
#define GEMM_SMEM (NST*STB)   // 96 KB

// ---------------- scratch (static device globals) ------------------------
__device__ float  g_logit[(size_t)BB*SS*HH];   // raw logits
__device__ int    g_maxi[BB*HH];               // encoded per-(b,h) max
__device__ int    g_flag[BB*NSEG*8];           // lookback flags
__device__ float  g_pref[(size_t)BB*NSEG*DD];  // inclusive column prefixes
__device__ float  g_vb [(size_t)BB*DD];
__device__ __half g_in_h[(size_t)MR*DD];       // inputs (half)
__device__ __half g_attn_h[(size_t)MR*DD];     // attn_out (half)
__device__ __half g_h1h[(size_t)MR*DD];        // ff1 hidden (half)
__device__ __half g_valTh[(size_t)DD*DD];
__device__ __half g_f1tTh[(size_t)DD*DD];
__device__ __half g_t1h [(size_t)DD*DD];
__device__ __half g_ff2Th[(size_t)DD*DD];
__device__ __half g_operh[(size_t)DD*DD];
__device__ __half g_owTh[(size_t)DD*DD];

// =================== helpers =============================================
__device__ __forceinline__ uint32_t smem_u32(const void* p) {
    uint32_t a;
    asm("{ .reg .u64 t; cvta.to.shared.u64 t, %1; cvt.u32.u64 %0, t; }"
        : "=r"(a) : "l"(p));
    return a;
}
__device__ __forceinline__ void cp16(uint32_t s, const void* g) {
    asm volatile("cp.async.cg.shared.global [%0], [%1], 16;"
                 :: "r"(s), "l"(g) : "memory");
}
__device__ __forceinline__ void cp_commit() {
    asm volatile("cp.async.commit_group;" ::: "memory");
}
template<int N>
__device__ __forceinline__ void cp_wait() {
    asm volatile("cp.async.wait_group %0;" :: "n"(N) : "memory");
}
__device__ __forceinline__ void ldm_x4(uint32_t* r, uint32_t addr) {
    asm volatile("ldmatrix.sync.aligned.m8n8.x4.shared.b16 {%0,%1,%2,%3}, [%4];"
                 : "=r"(r[0]), "=r"(r[1]), "=r"(r[2]), "=r"(r[3]) : "r"(addr));
}
__device__ __forceinline__ void mma16(float* d, const uint32_t* a, const uint32_t* b) {
    asm volatile(
        "mma.sync.aligned.m16n8k16.row.col.f32.f16.f16.f32 "
        "{%0,%1,%2,%3}, {%4,%5,%6,%7}, {%8,%9}, {%0,%1,%2,%3};"
        : "+f"(d[0]), "+f"(d[1]), "+f"(d[2]), "+f"(d[3])
        : "r"(a[0]), "r"(a[1]), "r"(a[2]), "r"(a[3]), "r"(b[0]), "r"(b[1]));
}
__device__ __forceinline__ uint32_t pack_h2(float a, float b) {
    __half2 h = __floats2half2_rn(a, b);
    return *reinterpret_cast<uint32_t*>(&h);
}
__device__ __forceinline__ int enc_f(float f) {
    int e = __float_as_int(f);
    return e >= 0 ? e : (e ^ 0x7FFFFFFF);
}
__device__ __forceinline__ float dec_f(int e) {
    return __int_as_float(e >= 0 ? e : (e ^ 0x7FFFFFFF));
}

// =================== fp16 mma.sync GEMM (ldmatrix + 3-stage) =============
// C[m,n] = sum_k A1[m,k]*B1[n,k] (+ A2[m,k]*B2[n,k] if A2), K=1024 per pair.
// MODE 1: half out
// MODE 2: half(relu(acc + aux2[(row>>12)*DD+col]))
// MODE 3: fp32: acc + aux1[row*DD+col] + aux2[col]
// MODE 5: fused causal-cumsum + attention scaling -> half attn_out (Cv)
//         decoupled-lookback via aux1 (pref) + flagp; logits/maxi/temp inputs
template<int MODE>
__global__ void __launch_bounds__(256, 2)
gemm_mma(const __half* __restrict__ A1, const __half* __restrict__ B1,
         const __half* __restrict__ A2, const __half* __restrict__ B2,
         void* __restrict__ Cv,
         float* __restrict__ aux1, const float* __restrict__ aux2,
         const float* __restrict__ logits, const int* __restrict__ maxi,
         const float* __restrict__ temp, int* __restrict__ flagp) {
    extern __shared__ char sm[];
    const uint32_t sbase = smem_u32(sm);
    const int tid = threadIdx.x, lane = tid & 31, wid = tid >> 5;
    const int wm = (wid & 3) * 32, wn = (wid >> 2) * 64;
    const int m0 = blockIdx.y * 128, n0 = blockIdx.x * 128;
    const int r4 = lane >> 2, l4 = lane & 3;
    const int nch = A2 ? 32 : 16;   // chunks of K=64 halves

    const int lrow = tid >> 1;
    const int lc0  = (tid & 1) * 4;
    const int lr7  = lrow & 7;

    const int a_row = wm + (lane & 15);
    const int a_hb  = lane >> 4;
    const int b_rlo = (lane & 7) + ((lane >> 4) & 1) * 8;
    const int b_hb  = (lane >> 3) & 1;

    float acc[2][8][4];
    #pragma unroll
    for (int i = 0; i < 2; i++)
        #pragma unroll
        for (int j = 0; j < 8; j++)
            #pragma unroll
            for (int q = 0; q < 4; q++) acc[i][j][q] = 0.f;

    auto load_chunk = [&](int c) {
        const __half* Ap = (c < 16) ? A1 : A2;
        const __half* Bp = (c < 16) ? B1 : B2;
        const int k0 = (c & 15) * 64;
        const uint32_t st = sbase + (uint32_t)((c % NST) * STB);
        const __half* ga = Ap + (size_t)(m0 + lrow) * DD + k0 + lc0 * 8;
        const __half* gb = Bp + (size_t)(n0 + lrow) * DD + k0 + lc0 * 8;
        const uint32_t rowoff = (uint32_t)lrow * 128u;
        #pragma unroll
        for (int q = 0; q < 4; q++) {
            uint32_t sc = (uint32_t)(((lc0 + q) ^ lr7) << 4);
            cp16(st + rowoff + sc,           ga + q * 8);
            cp16(st + 16384u + rowoff + sc,  gb + q * 8);
        }
        cp_commit();
    };

    load_chunk(0);
    load_chunk(1);

    for (int c = 0; c < nch; c++) {
        if (c + 1 < nch) cp_wait<1>(); else cp_wait<0>();
        __syncthreads();
        if (c + 2 < nch) load_chunk(c + 2);

        const uint32_t Ab = sbase + (uint32_t)((c % NST) * STB);
        const uint32_t Bb = Ab + 16384u;

        uint32_t bgbuf[2][4][4];
        #pragma unroll
        for (int g = 0; g < 4; g++) {
            int row = wn + g * 16 + b_rlo;
            ldm_x4(bgbuf[0][g], Bb + row * 128 + ((b_hb ^ (row & 7)) << 4));
        }
        #pragma unroll
        for (int ks = 0; ks < 4; ks++) {
            uint32_t a[2][4];
            #pragma unroll
            for (int i = 0; i < 2; i++) {
                int row = a_row + i * 16;
                int ch = 2 * ks + a_hb;
                ldm_x4(a[i], Ab + row * 128 + ((ch ^ (row & 7)) << 4));
            }
            if (ks < 3) {
                #pragma unroll
                for (int g = 0; g < 4; g++) {
                    int row = wn + g * 16 + b_rlo;
                    int ch = 2 * (ks + 1) + b_hb;
                    ldm_x4(bgbuf[(ks + 1) & 1][g],
                           Bb + row * 128 + ((ch ^ (row & 7)) << 4));
                }
            }
            #pragma unroll
            for (int i = 0; i < 2; i++)
                #pragma unroll
                for (int j = 0; j < 8; j++)
                    mma16(acc[i][j], a[i], &bgbuf[ks & 1][j >> 1][(j & 1) * 2]);
        }
    }

    if (MODE == 5) {
        // ---- fused causal cumsum + attention scaling ----
        __syncthreads();                  // all warps done with stage smem
        float* tile  = (float*)sm;        // [128][132] fp32
        float* satt  = tile + 128 * 132;  // [128][2]
        float* sexcl = satt + 256;        // [128]
        const int b   = m0 >> 12;
        const int seg = (m0 >> 7) & (NSEG - 1);
        const int h0  = n0 >> 6;          // first of the 2 heads in this tile

        // 1. dump acc tile to smem
        #pragma unroll
        for (int i = 0; i < 2; i++) {
            int lr = wm + i * 16 + r4;
            #pragma unroll
            for (int j = 0; j < 8; j++) {
                int lc = wn + j * 8 + l4 * 2;
                tile[lr * 132 + lc]           = acc[i][j][0];
                tile[lr * 132 + lc + 1]       = acc[i][j][1];
                tile[(lr + 8) * 132 + lc]     = acc[i][j][2];
                tile[(lr + 8) * 132 + lc + 1] = acc[i][j][3];
            }
        }
        __syncthreads();

        // 2. phase A cumsum (rows 0..63) + satt computation
        if (tid < 128) {
            int col = tid;
            float run = 0.f;
            #pragma unroll 8
            for (int r = 0; r < 64; r++) {
                run += tile[r * 132 + col];
                tile[r * 132 + col] = run;
            }
        } else {
            int r = tid - 128;
            const float* lp = logits + (size_t)(m0 + r) * HH + h0;
            float mh0 = dec_f(maxi[b * HH + h0]);
            float mh1 = dec_f(maxi[b * HH + h0 + 1]);
            satt[r * 2 + 0] = expf((lp[0] - mh0) * temp[h0]);
            satt[r * 2 + 1] = expf((lp[1] - mh1) * temp[h0 + 1]);
        }
        __syncthreads();

        // 3. phase B cumsum (rows 64..127)
        if (tid < 128) {
            int col = tid;
            float run = tile[63 * 132 + col];
            #pragma unroll 8
            for (int r = 64; r < 128; r++) {
                run += tile[r * 132 + col];
                tile[r * 132 + col] = run;
            }
        }
        __syncthreads();

        // 4. lookback: wait for predecessor's inclusive prefix
        const int fidx = (b * NSEG + seg) * 8 + blockIdx.x;
        if (seg > 0 && tid == 0) {
            volatile int* vf = &flagp[fidx - 8];
            while (*vf == 0) { }
        }
        __syncthreads();
        if (tid < 128) {
            if (seg > 0)
                sexcl[tid] = __ldcg(&aux1[((size_t)(b * NSEG + seg - 1)) * DD + n0 + tid]);
            else
                sexcl[tid] = 0.f;
        }
        __syncthreads();

        // 5. publish inclusive prefix + flag
        if (seg < NSEG - 1 && tid < 128) {
            float incl = sexcl[tid] + tile[127 * 132 + tid];
            __stcg(&aux1[((size_t)(b * NSEG + seg)) * DD + n0 + tid], incl);
        }
        __threadfence();
        __syncthreads();
        if (seg < NSEG - 1 && tid == 0) atomicExch(&flagp[fidx], 1);

        // 6. scale + coalesced half write-out
        __half* attnh = (__half*)Cv;
        #pragma unroll 4
        for (int it = 0; it < 32; it++) {
            int r = it * 4 + (tid >> 6);
            int cp = (tid & 63) * 2;
            float v0 = sexcl[cp]     + tile[r * 132 + cp];
            float v1 = sexcl[cp + 1] + tile[r * 132 + cp + 1];
            int hl = cp >> 6;
            float a = satt[r * 2 + hl];
            float cnt = (float)(seg * SEG + r + 1);
            float s = __fdividef(a, a * cnt + 1e-30f);
            *(uint32_t*)(attnh + (size_t)(m0 + r) * DD + n0 + cp) =
                pack_h2(v0 * s, v1 * s);
        }
        return;
    }

    // standard epilogues
    float* Cf = (float*)Cv;
    __half* Ch = (__half*)Cv;
    #pragma unroll
    for (int i = 0; i < 2; i++) {
        int grow = m0 + wm + i * 16 + r4;
        #pragma unroll
        for (int j = 0; j < 8; j++) {
            int gcol = n0 + wn + j * 8 + l4 * 2;
            float v0 = acc[i][j][0], v1 = acc[i][j][1];
            float v2 = acc[i][j][2], v3 = acc[i][j][3];
            if (MODE == 1) {
                *(uint32_t*)(Ch + (size_t)grow * DD + gcol)       = pack_h2(v0, v1);
                *(uint32_t*)(Ch + (size_t)(grow + 8) * DD + gcol) = pack_h2(v2, v3);
            }
            if (MODE == 2) {
                const float* vb0 = aux2 + (size_t)(grow >> 12) * DD + gcol;
                v0 = fmaxf(v0 + vb0[0], 0.f);
                v1 = fmaxf(v1 + vb0[1], 0.f);
                v2 = fmaxf(v2 + vb0[0], 0.f);
                v3 = fmaxf(v3 + vb0[1], 0.f);
                *(uint32_t*)(Ch + (size_t)grow * DD + gcol)       = pack_h2(v0, v1);
                *(uint32_t*)(Ch + (size_t)(grow + 8) * DD + gcol) = pack_h2(v2, v3);
            }
            if (MODE == 3) {
                const float* rp0 = aux1 + (size_t)grow * DD + gcol;
                const float* rp1 = aux1 + (size_t)(grow + 8) * DD + gcol;
                v0 += rp0[0] + aux2[gcol];
                v1 += rp0[1] + aux2[gcol + 1];
                v2 += rp1[0] + aux2[gcol];
                v3 += rp1[1] + aux2[gcol + 1];
                *(float2*)(Cf + (size_t)grow * DD + gcol)       = make_float2(v0, v1);
                *(float2*)(Cf + (size_t)(grow + 8) * DD + gcol) = make_float2(v2, v3);
            }
        }
    }
}

// ====== batched prep: 4 transposes + operator cvt + maxi/flag reset ======
__global__ void k_prep(const float* __restrict__ values, const float* __restrict__ ff1,
                       const float* __restrict__ ff2, const float* __restrict__ oper,
                       __half* __restrict__ valT, __half* __restrict__ f1tT,
                       __half* __restrict__ t1, __half* __restrict__ ff2T,
                       __half* __restrict__ operh, int* __restrict__ maxi,
                       int* __restrict__ flags) {
    int z = blockIdx.z;
    int c0 = blockIdx.x * 32, r0 = blockIdx.y * 32;
    int x = threadIdx.x, y = threadIdx.y;
    if (z == 4) {
        if (blockIdx.x == 0 && blockIdx.y == 0) {
            int flat = y * 32 + x;
            if (flat < BB * HH) maxi[flat] = INT_MIN;
            for (int i = flat; i < BB * NSEG * 8; i += 256) flags[i] = 0;
        }
        #pragma unroll
        for (int j = 0; j < 32; j += 8) {
            size_t idx = (size_t)(r0 + y + j) * DD + c0 + x;
            operh[idx] = __float2half_rn(oper[idx]);
        }
        return;
    }
    const float* src = (z == 0) ? values : (z == 1) ? ff1
                      : (z == 2) ? (ff1 + (size_t)DD * DD) : ff2;
    __half* dst = (z == 0) ? valT : (z == 1) ? f1tT : (z == 2) ? t1 : ff2T;
    __shared__ float t[32][33];
    #pragma unroll
    for (int j = 0; j < 32; j += 8)
        t[y + j][x] = src[(size_t)(r0 + y + j) * DD + c0 + x];
    __syncthreads();
    #pragma unroll
    for (int j = 0; j < 32; j += 8)
        dst[(size_t)(c0 + y + j) * DD + r0 + x] = __float2half_rn(t[x][y + j]);
}

// =================== vb = vector @ ff1_bot + b1 (half t1) ================
__global__ void k_vb(const float* __restrict__ vec, const __half* __restrict__ t1,
                     const float* __restrict__ bias, float* __restrict__ vb) {
    __shared__ float sv[DD];
    int b = blockIdx.y;
    for (int i = threadIdx.x; i < DD; i += 256) sv[i] = vec[(size_t)b * DD + i];
    __syncthreads();
    int d = blockIdx.x * 256 + threadIdx.x;
    const __half2* tp = (const __half2*)(t1 + (size_t)d * DD);
    float s = 0.f;
    #pragma unroll 4
    for (int i = 0; i < DD / 2; i++) {
        float2 a = __half22float2(tp[i]);
        s += a.x * sv[2 * i] + a.y * sv[2 * i + 1];
    }
    vb[(size_t)b * DD + d] = s + bias[d];
}

// ===== logits + half-cvt of inputs + per-(b,h) max via atomicMax =========
__global__ void k_logits(const float* __restrict__ inputs,
                         const float* __restrict__ W,
                         float* __restrict__ logits,
                         __half* __restrict__ inh,
                         int* __restrict__ maxi) {
    extern __shared__ float Wt[];   // [16][1024] + 16 ints tail
    int* smax = (int*)(Wt + DD * HH);
    int tid = threadIdx.x;
    if (tid < HH) smax[tid] = INT_MIN;
    for (int idx = tid; idx < DD * HH; idx += 256) {
        int i = idx >> 4, h = idx & 15;
        Wt[h * DD + i] = W[idx];
    }
    __syncthreads();
    int warp = tid >> 5, lane = tid & 31;
    float rowmax[HH];
    #pragma unroll
    for (int h = 0; h < HH; h++) rowmax[h] = -3.4e38f;
    for (int rr = 0; rr < 4; rr++) {
        int r = blockIdx.x * 32 + warp * 4 + rr;
        const float4* xp = (const float4*)(inputs + (size_t)r * DD);
        uint2* hp = (uint2*)(inh + (size_t)r * DD);
        float acc[HH];
        #pragma unroll
        for (int h = 0; h < HH; h++) acc[h] = 0.f;
        #pragma unroll
        for (int j = 0; j < 8; j++) {
            float4 x = xp[lane + 32 * j];
            hp[lane + 32 * j] = make_uint2(pack_h2(x.x, x.y), pack_h2(x.z, x.w));
            int i0 = (lane + 32 * j) * 4;
            #pragma unroll
            for (int h = 0; h < HH; h++) {
                float4 w = *(const float4*)&Wt[h * DD + i0];
                acc[h] += x.x * w.x + x.y * w.y + x.z * w.z + x.w * w.w;
            }
        }
        #pragma unroll
        for (int h = 0; h < HH; h++) {
            #pragma unroll
            for (int o = 16; o > 0; o >>= 1)
                acc[h] += __shfl_xor_sync(0xffffffffu, acc[h], o);
        }
        if (lane == 0) {
            #pragma unroll
            for (int h = 0; h < HH; h++) {
                logits[(size_t)r * HH + h] = acc[h];
                rowmax[h] = fmaxf(rowmax[h], acc[h]);
            }
        }
    }
    if (lane == 0) {
        #pragma unroll
        for (int h = 0; h < HH; h++) atomicMax(&smax[h], enc_f(rowmax[h]));
    }
    __syncthreads();
    if (tid < HH) {
        int b = (blockIdx.x * 32) >> 12;
        atomicMax(&maxi[b * HH + tid], smax[tid]);
    }
}

// ---------------- LayerNorm (in place over d_out rows) ------------------
__global__ void k_ln(float* __restrict__ X, const float* __restrict__ g,
                     const float* __restrict__ be) {
    int r = blockIdx.x;
    float* p = X + (size_t)r * DD;
    int i = threadIdx.x * 4;
    float4 x = *(const float4*)(p + i);
    __shared__ float red[256];
    float s = x.x + x.y + x.z + x.w;
    red[threadIdx.x] = s; __syncthreads();
    for (int o = 128; o > 0; o >>= 1) {
        if (threadIdx.x < o) red[threadIdx.x] += red[threadIdx.x + o];
        __syncthreads();
    }
    float mean = red[0] * (1.f / DD);
    __syncthreads();
    float d0 = x.x - mean, d1 = x.y - mean, d2 = x.z - mean, d3 = x.w - mean;
    red[threadIdx.x] = d0 * d0 + d1 * d1 + d2 * d2 + d3 * d3;
    __syncthreads();
    for (int o = 128; o > 0; o >>= 1) {
        if (threadIdx.x < o) red[threadIdx.x] += red[threadIdx.x + o];
        __syncthreads();
    }
    float inv = rsqrtf(red[0] * (1.f / DD) + 1e-6f);
    float4 o4;
    o4.x = d0 * inv * g[i + 0] + be[i + 0];
    o4.y = d1 * inv * g[i + 1] + be[i + 1];
    o4.z = d2 * inv * g[i + 2] + be[i + 2];
    o4.w = d3 * inv * g[i + 3] + be[i + 3];
    *(float4*)(p + i) = o4;
}

// ---------------- launcher ----------------------------------------------
extern "C" void kernel_launch(void* const* d_in, const int* in_sizes, int n_in,
                              void* d_out, int out_size) {
    (void)in_sizes; (void)n_in; (void)out_size;
    const float* inputs   = (const float*)d_in[0];
    const float* vector   = (const float*)d_in[1];
    const float* attw     = (const float*)d_in[2];
    const float* temp     = (const float*)d_in[3];
    const float* values   = (const float*)d_in[4];
    const float* oper     = (const float*)d_in[5];
    const float* ff1      = (const float*)d_in[6];
    const float* ff1_bias = (const float*)d_in[7];
    const float* ff2      = (const float*)d_in[8];
    const float* ff2_bias = (const float*)d_in[9];
    const float* ln_gamma = (const float*)d_in[10];
    const float* ln_beta  = (const float*)d_in[11];
    float* out = (float*)d_out;

    float *logit_p, *pref_p, *vb_p;
    int *maxi_p, *flag_p;
    __half *inh_p, *attnh_p, *h1h_p, *valT_p, *f1tT_p, *t1_p, *ff2T_p, *operh_p, *owT_p;
    cudaGetSymbolAddress((void**)&logit_p, g_logit);
    cudaGetSymbolAddress((void**)&maxi_p,  g_maxi);
    cudaGetSymbolAddress((void**)&flag_p,  g_flag);
    cudaGetSymbolAddress((void**)&pref_p,  g_pref);
    cudaGetSymbolAddress((void**)&vb_p,    g_vb);
    cudaGetSymbolAddress((void**)&inh_p,   g_in_h);
    cudaGetSymbolAddress((void**)&attnh_p, g_attn_h);
    cudaGetSymbolAddress((void**)&h1h_p,   g_h1h);
    cudaGetSymbolAddress((void**)&valT_p,  g_valTh);
    cudaGetSymbolAddress((void**)&f1tT_p,  g_f1tTh);
    cudaGetSymbolAddress((void**)&t1_p,    g_t1h);
    cudaGetSymbolAddress((void**)&ff2T_p,  g_ff2Th);
    cudaGetSymbolAddress((void**)&operh_p, g_operh);
    cudaGetSymbolAddress((void**)&owT_p,   g_owTh);

    cudaFuncSetAttribute(gemm_mma<1>, cudaFuncAttributeMaxDynamicSharedMemorySize, GEMM_SMEM);
    cudaFuncSetAttribute(gemm_mma<2>, cudaFuncAttributeMaxDynamicSharedMemorySize, GEMM_SMEM);
    cudaFuncSetAttribute(gemm_mma<3>, cudaFuncAttributeMaxDynamicSharedMemorySize, GEMM_SMEM);
    cudaFuncSetAttribute(gemm_mma<5>, cudaFuncAttributeMaxDynamicSharedMemorySize, GEMM_SMEM);
    cudaFuncSetAttribute(k_logits, cudaFuncAttributeMaxDynamicSharedMemorySize, 65536 + 64);

    // 0: batched prep (4 transposes + oper cvt + maxi/flag reset)
    k_prep<<<dim3(32, 32, 5), dim3(32, 8)>>>(values, ff1, ff2, oper,
                                             valT_p, f1tT_p, t1_p, ff2T_p,
                                             operh_p, maxi_p, flag_p);
    // 1: logits + half inputs + per-(b,h) max
    k_logits<<<MR / 32, 256, 65536 + 64>>>(inputs, attw, logit_p, inh_p, maxi_p);
    // 2: vb = vector @ ff1_bot + b1
    k_vb<<<dim3(DD / 256, BB), 256>>>(vector, t1_p, ff1_bias, vb_p);
    // 3: fused v-GEMM + causal cumsum + att scaling -> half attn_out
    gemm_mma<5><<<dim3(8, MR / 128), 256, GEMM_SMEM>>>(inh_p, valT_p, nullptr, nullptr,
                                                       attnh_p, pref_p, nullptr,
                                                       logit_p, maxi_p, temp, flag_p);
    // 4: owT[n][f] = sum_dv t1[n][dv] * operator[f][dv]  (half out)
    gemm_mma<1><<<dim3(8, 8), 256, GEMM_SMEM>>>(t1_p, operh_p, nullptr, nullptr,
                                                owT_p, nullptr, nullptr,
                                                nullptr, nullptr, nullptr, nullptr);
    // 5: h1 = relu(inputs@ff1_top + attn@OW + vb)  (half out)
    gemm_mma<2><<<dim3(8, MR / 128), 256, GEMM_SMEM>>>(inh_p, f1tT_p, attnh_p, owT_p,
                                                       h1h_p, nullptr, vb_p,
                                                       nullptr, nullptr, nullptr, nullptr);
    // 6: out = h1 @ ff2 + b2 + inputs (fp32)
    gemm_mma<3><<<dim3(8, MR / 128), 256, GEMM_SMEM>>>(h1h_p, ff2T_p, nullptr, nullptr,
                                                       out, (float*)inputs, ff2_bias,
                                                       nullptr, nullptr, nullptr, nullptr);
    // 7: LayerNorm in place
    k_ln<<<MR, 256>>>(out, ln_gamma, ln_beta);
}

// round 17
// speedup vs baseline: 1.0271x; 1.0271x over previous
#include <cuda_runtime.h>
#include <cuda_fp16.h>
#include <math.h>
#include <stdint.h>
#include <limits.h>

// Problem constants
#define BB   4
#define SS   4096
#define DD   1024
#define HH   16
#define MR   (BB*SS)          // 16384 rows
#define SEG  128
#define NSEG (SS/SEG)         // 32

#define NST  3                // pipeline stages
#define STB  32768            // bytes per stage (A 16KB + B 16KB)
#define GEMM_SMEM (NST*STB)   // 96 KB

// ---------------- scratch (static device globals) ------------------------
__device__ float  g_logit[(size_t)BB*SS*HH];   // raw logits
__device__ int    g_maxi[BB*HH];               // encoded per-(b,h) max
__device__ int    g_flag[BB*NSEG*8];           // lookback flags (0/1=agg/2=incl)
__device__ float  g_pref[(size_t)BB*NSEG*DD*2]; // [0]: inclusive, [1]: aggregate
__device__ float  g_vb [(size_t)BB*DD];
__device__ __half g_in_h[(size_t)MR*DD];       // inputs (half)
__device__ __half g_attn_h[(size_t)MR*DD];     // attn_out (half)
__device__ __half g_h1h[(size_t)MR*DD];        // ff1 hidden (half)
__device__ __half g_valTh[(size_t)DD*DD];
__device__ __half g_f1tTh[(size_t)DD*DD];
__device__ __half g_t1h [(size_t)DD*DD];
__device__ __half g_ff2Th[(size_t)DD*DD];
__device__ __half g_operh[(size_t)DD*DD];
__device__ __half g_owTh[(size_t)DD*DD];

// =================== helpers =============================================
__device__ __forceinline__ uint32_t smem_u32(const void* p) {
    uint32_t a;
    asm("{ .reg .u64 t; cvta.to.shared.u64 t, %1; cvt.u32.u64 %0, t; }"
        : "=r"(a) : "l"(p));
    return a;
}
__device__ __forceinline__ void cp16(uint32_t s, const void* g) {
    asm volatile("cp.async.cg.shared.global [%0], [%1], 16;"
                 :: "r"(s), "l"(g) : "memory");
}
__device__ __forceinline__ void cp_commit() {
    asm volatile("cp.async.commit_group;" ::: "memory");
}
template<int N>
__device__ __forceinline__ void cp_wait() {
    asm volatile("cp.async.wait_group %0;" :: "n"(N) : "memory");
}
__device__ __forceinline__ void ldm_x4(uint32_t* r, uint32_t addr) {
    asm volatile("ldmatrix.sync.aligned.m8n8.x4.shared.b16 {%0,%1,%2,%3}, [%4];"
                 : "=r"(r[0]), "=r"(r[1]), "=r"(r[2]), "=r"(r[3]) : "r"(addr));
}
__device__ __forceinline__ void mma16(float* d, const uint32_t* a, const uint32_t* b) {
    asm volatile(
        "mma.sync.aligned.m16n8k16.row.col.f32.f16.f16.f32 "
        "{%0,%1,%2,%3}, {%4,%5,%6,%7}, {%8,%9}, {%0,%1,%2,%3};"
        : "+f"(d[0]), "+f"(d[1]), "+f"(d[2]), "+f"(d[3])
        : "r"(a[0]), "r"(a[1]), "r"(a[2]), "r"(a[3]), "r"(b[0]), "r"(b[1]));
}
__device__ __forceinline__ uint32_t pack_h2(float a, float b) {
    __half2 h = __floats2half2_rn(a, b);
    return *reinterpret_cast<uint32_t*>(&h);
}
__device__ __forceinline__ int enc_f(float f) {
    int e = __float_as_int(f);
    return e >= 0 ? e : (e ^ 0x7FFFFFFF);
}
__device__ __forceinline__ float dec_f(int e) {
    return __int_as_float(e >= 0 ? e : (e ^ 0x7FFFFFFF));
}

// =================== fp16 mma.sync GEMM (ldmatrix + 3-stage) =============
// MODE 2: half(relu(acc + aux2[(row>>12)*DD+col]))  (dual-K: A1/B1 then A2/B2)
// MODE 3: fp32: acc + aux1[row*DD+col] + aux2[col]
// MODE 5: by<128: v-GEMM + fused causal cumsum + att scaling -> half (Cv)
//         by>=128: owT GEMM with operands A2/B2 -> half aux2 (tail blocks)
template<int MODE>
__global__ void __launch_bounds__(256, 2)
gemm_mma(const __half* __restrict__ A1, const __half* __restrict__ B1,
         const __half* __restrict__ A2, const __half* __restrict__ B2,
         void* __restrict__ Cv,
         float* __restrict__ aux1, const float* __restrict__ aux2,
         const float* __restrict__ logits, const int* __restrict__ maxi,
         const float* __restrict__ temp, int* __restrict__ flagp) {
    extern __shared__ char sm[];
    const uint32_t sbase = smem_u32(sm);
    const int tid = threadIdx.x, lane = tid & 31, wid = tid >> 5;
    const int wm = (wid & 3) * 32, wn = (wid >> 2) * 64;
    const int n0 = blockIdx.x * 128;
    const int r4 = lane >> 2, l4 = lane & 3;
    const int nch = (MODE == 2) ? 32 : 16;

    bool owt = false;
    const __half* Ap = A1;
    const __half* Bp = B1;
    int m0 = blockIdx.y * 128;
    if (MODE == 5 && blockIdx.y >= 128) {
        owt = true;
        Ap = A2; Bp = B2;
        m0 = (blockIdx.y - 128) * 128;
    }

    const int lrow = tid >> 1;
    const int lc0  = (tid & 1) * 4;
    const int lr7  = lrow & 7;

    const int a_row = wm + (lane & 15);
    const int a_hb  = lane >> 4;
    const int b_rlo = (lane & 7) + ((lane >> 4) & 1) * 8;
    const int b_hb  = (lane >> 3) & 1;

    float acc[2][8][4];
    #pragma unroll
    for (int i = 0; i < 2; i++)
        #pragma unroll
        for (int j = 0; j < 8; j++)
            #pragma unroll
            for (int q = 0; q < 4; q++) acc[i][j][q] = 0.f;

    auto load_chunk = [&](int c) {
        const __half* Aq = (MODE == 2 && c >= 16) ? A2 : Ap;
        const __half* Bq = (MODE == 2 && c >= 16) ? B2 : Bp;
        const int k0 = (c & 15) * 64;
        const uint32_t st = sbase + (uint32_t)((c % NST) * STB);
        const __half* ga = Aq + (size_t)(m0 + lrow) * DD + k0 + lc0 * 8;
        const __half* gb = Bq + (size_t)(n0 + lrow) * DD + k0 + lc0 * 8;
        const uint32_t rowoff = (uint32_t)lrow * 128u;
        #pragma unroll
        for (int q = 0; q < 4; q++) {
            uint32_t sc = (uint32_t)(((lc0 + q) ^ lr7) << 4);
            cp16(st + rowoff + sc,           ga + q * 8);
            cp16(st + 16384u + rowoff + sc,  gb + q * 8);
        }
        cp_commit();
    };

    load_chunk(0);
    load_chunk(1);

    for (int c = 0; c < nch; c++) {
        if (c + 1 < nch) cp_wait<1>(); else cp_wait<0>();
        __syncthreads();
        if (c + 2 < nch) load_chunk(c + 2);

        const uint32_t Ab = sbase + (uint32_t)((c % NST) * STB);
        const uint32_t Bb = Ab + 16384u;

        uint32_t bgbuf[2][4][4];
        #pragma unroll
        for (int g = 0; g < 4; g++) {
            int row = wn + g * 16 + b_rlo;
            ldm_x4(bgbuf[0][g], Bb + row * 128 + ((b_hb ^ (row & 7)) << 4));
        }
        #pragma unroll
        for (int ks = 0; ks < 4; ks++) {
            uint32_t a[2][4];
            #pragma unroll
            for (int i = 0; i < 2; i++) {
                int row = a_row + i * 16;
                int ch = 2 * ks + a_hb;
                ldm_x4(a[i], Ab + row * 128 + ((ch ^ (row & 7)) << 4));
            }
            if (ks < 3) {
                #pragma unroll
                for (int g = 0; g < 4; g++) {
                    int row = wn + g * 16 + b_rlo;
                    int ch = 2 * (ks + 1) + b_hb;
                    ldm_x4(bgbuf[(ks + 1) & 1][g],
                           Bb + row * 128 + ((ch ^ (row & 7)) << 4));
                }
            }
            #pragma unroll
            for (int i = 0; i < 2; i++)
                #pragma unroll
                for (int j = 0; j < 8; j++)
                    mma16(acc[i][j], a[i], &bgbuf[ks & 1][j >> 1][(j & 1) * 2]);
        }
    }

    if (MODE == 5 && owt) {
        // owT tail blocks: plain half-out epilogue to aux2
        __half* owtp = (__half*)const_cast<float*>(aux2);
        #pragma unroll
        for (int i = 0; i < 2; i++) {
            int grow = m0 + wm + i * 16 + r4;
            #pragma unroll
            for (int j = 0; j < 8; j++) {
                int gcol = n0 + wn + j * 8 + l4 * 2;
                *(uint32_t*)(owtp + (size_t)grow * DD + gcol) =
                    pack_h2(acc[i][j][0], acc[i][j][1]);
                *(uint32_t*)(owtp + (size_t)(grow + 8) * DD + gcol) =
                    pack_h2(acc[i][j][2], acc[i][j][3]);
            }
        }
        return;
    }

    if (MODE == 5) {
        // ---- fused causal cumsum (decoupled lookback) + att scaling ----
        __syncthreads();                  // mainloop smem free
        float* tile  = (float*)sm;        // [128][132]
        float* satt  = tile + 128 * 132;  // [128][2]
        float* sexcl = satt + 256;        // [128]
        __shared__ int sstate;
        const int b   = m0 >> 12;
        const int seg = (m0 >> 7) & (NSEG - 1);
        const int h0  = n0 >> 6;
        const int fidx = (b * NSEG + seg) * 8 + blockIdx.x;
        float* pref = aux1;                                   // inclusive
        float* aggp = aux1 + (size_t)BB * NSEG * DD;          // aggregate

        // P0: dump acc tile
        #pragma unroll
        for (int i = 0; i < 2; i++) {
            int lr = wm + i * 16 + r4;
            #pragma unroll
            for (int j = 0; j < 8; j++) {
                int lc = wn + j * 8 + l4 * 2;
                tile[lr * 132 + lc]           = acc[i][j][0];
                tile[lr * 132 + lc + 1]       = acc[i][j][1];
                tile[(lr + 8) * 132 + lc]     = acc[i][j][2];
                tile[(lr + 8) * 132 + lc + 1] = acc[i][j][3];
            }
        }
        __syncthreads();

        // P1: per-half local cumsums (depth 64, 2 threads per column)
        {
            int col = tid & 127;
            int r0 = (tid >> 7) * 64;     // 0 or 64
            float run = 0.f;
            #pragma unroll 8
            for (int r = r0; r < r0 + 64; r++) {
                run += tile[r * 132 + col];
                tile[r * 132 + col] = run;
            }
        }
        __syncthreads();

        // P2: publish aggregate (t<128); satt (t>=128)
        float total = 0.f;
        if (tid < 128) {
            total = tile[63 * 132 + tid] + tile[127 * 132 + tid];
            if (seg < NSEG - 1) {
                size_t off = ((size_t)(b * NSEG + seg)) * DD + n0 + tid;
                if (seg == 0) __stcg(&pref[off], total);
                else          __stcg(&aggp[off], total);
            }
        } else {
            int r = tid - 128;
            const float* lp = logits + (size_t)(m0 + r) * HH + h0;
            float mh0 = dec_f(maxi[b * HH + h0]);
            float mh1 = dec_f(maxi[b * HH + h0 + 1]);
            satt[r * 2 + 0] = expf((lp[0] - mh0) * temp[h0]);
            satt[r * 2 + 1] = expf((lp[1] - mh1) * temp[h0 + 1]);
        }
        __threadfence();
        __syncthreads();
        if (tid == 0 && seg < NSEG - 1)
            atomicExch(&flagp[fidx], (seg == 0) ? 2 : 1);

        // P3: lookback (back-scan aggregates until an inclusive)
        float excl = 0.f;
        if (seg > 0) {
            int p = seg - 1;
            while (true) {
                if (tid == 0) {
                    volatile int* vf = &flagp[(b * NSEG + p) * 8 + blockIdx.x];
                    int f;
                    do { f = *vf; } while (f == 0);
                    sstate = f;
                }
                __syncthreads();
                int st = sstate;
                __threadfence();
                if (tid < 128) {
                    size_t off = ((size_t)(b * NSEG + p)) * DD + n0 + tid;
                    excl += (st == 2) ? __ldcg(&pref[off]) : __ldcg(&aggp[off]);
                }
                __syncthreads();
                if (st == 2) break;
                p--;
            }
            // P4: publish inclusive
            if (seg < NSEG - 1) {
                if (tid < 128) {
                    size_t off = ((size_t)(b * NSEG + seg)) * DD + n0 + tid;
                    __stcg(&pref[off], excl + total);
                }
                __threadfence();
                __syncthreads();
                if (tid == 0) atomicExch(&flagp[fidx], 2);
            }
        }

        // P5: stage excl
        if (tid < 128) sexcl[tid] = excl;
        __syncthreads();

        // P6: scale + coalesced half write-out
        __half* attnh = (__half*)Cv;
        #pragma unroll 4
        for (int it = 0; it < 32; it++) {
            int r = it * 4 + (tid >> 6);
            int cp = (tid & 63) * 2;
            float up0 = (r >= 64) ? tile[63 * 132 + cp]     : 0.f;
            float up1 = (r >= 64) ? tile[63 * 132 + cp + 1] : 0.f;
            float v0 = sexcl[cp]     + up0 + tile[r * 132 + cp];
            float v1 = sexcl[cp + 1] + up1 + tile[r * 132 + cp + 1];
            int hl = cp >> 6;
            float a = satt[r * 2 + hl];
            float cnt = (float)(seg * SEG + r + 1);
            float s = __fdividef(a, a * cnt + 1e-30f);
            *(uint32_t*)(attnh + (size_t)(m0 + r) * DD + n0 + cp) =
                pack_h2(v0 * s, v1 * s);
        }
        return;
    }

    // standard epilogues
    float* Cf = (float*)Cv;
    __half* Ch = (__half*)Cv;
    #pragma unroll
    for (int i = 0; i < 2; i++) {
        int grow = m0 + wm + i * 16 + r4;
        #pragma unroll
        for (int j = 0; j < 8; j++) {
            int gcol = n0 + wn + j * 8 + l4 * 2;
            float v0 = acc[i][j][0], v1 = acc[i][j][1];
            float v2 = acc[i][j][2], v3 = acc[i][j][3];
            if (MODE == 2) {
                const float* vb0 = aux2 + (size_t)(grow >> 12) * DD + gcol;
                v0 = fmaxf(v0 + vb0[0], 0.f);
                v1 = fmaxf(v1 + vb0[1], 0.f);
                v2 = fmaxf(v2 + vb0[0], 0.f);
                v3 = fmaxf(v3 + vb0[1], 0.f);
                *(uint32_t*)(Ch + (size_t)grow * DD + gcol)       = pack_h2(v0, v1);
                *(uint32_t*)(Ch + (size_t)(grow + 8) * DD + gcol) = pack_h2(v2, v3);
            }
            if (MODE == 3) {
                const float* rp0 = aux1 + (size_t)grow * DD + gcol;
                const float* rp1 = aux1 + (size_t)(grow + 8) * DD + gcol;
                v0 += rp0[0] + aux2[gcol];
                v1 += rp0[1] + aux2[gcol + 1];
                v2 += rp1[0] + aux2[gcol];
                v3 += rp1[1] + aux2[gcol + 1];
                *(float2*)(Cf + (size_t)grow * DD + gcol)       = make_float2(v0, v1);
                *(float2*)(Cf + (size_t)(grow + 8) * DD + gcol) = make_float2(v2, v3);
            }
        }
    }
}

// ====== batched prep: 4 transposes + operator cvt + maxi/flag reset ======
__global__ void k_prep(const float* __restrict__ values, const float* __restrict__ ff1,
                       const float* __restrict__ ff2, const float* __restrict__ oper,
                       __half* __restrict__ valT, __half* __restrict__ f1tT,
                       __half* __restrict__ t1, __half* __restrict__ ff2T,
                       __half* __restrict__ operh, int* __restrict__ maxi,
                       int* __restrict__ flags) {
    int z = blockIdx.z;
    int c0 = blockIdx.x * 32, r0 = blockIdx.y * 32;
    int x = threadIdx.x, y = threadIdx.y;
    if (z == 4) {
        if (blockIdx.x == 0 && blockIdx.y == 0) {
            int flat = y * 32 + x;
            if (flat < BB * HH) maxi[flat] = INT_MIN;
            for (int i = flat; i < BB * NSEG * 8; i += 256) flags[i] = 0;
        }
        #pragma unroll
        for (int j = 0; j < 32; j += 8) {
            size_t idx = (size_t)(r0 + y + j) * DD + c0 + x;
            operh[idx] = __float2half_rn(oper[idx]);
        }
        return;
    }
    const float* src = (z == 0) ? values : (z == 1) ? ff1
                      : (z == 2) ? (ff1 + (size_t)DD * DD) : ff2;
    __half* dst = (z == 0) ? valT : (z == 1) ? f1tT : (z == 2) ? t1 : ff2T;
    __shared__ float t[32][33];
    #pragma unroll
    for (int j = 0; j < 32; j += 8)
        t[y + j][x] = src[(size_t)(r0 + y + j) * DD + c0 + x];
    __syncthreads();
    #pragma unroll
    for (int j = 0; j < 32; j += 8)
        dst[(size_t)(c0 + y + j) * DD + r0 + x] = __float2half_rn(t[x][y + j]);
}

// =================== vb = vector @ ff1_bot + b1 (half t1) ================
__global__ void k_vb(const float* __restrict__ vec, const __half* __restrict__ t1,
                     const float* __restrict__ bias, float* __restrict__ vb) {
    __shared__ float sv[DD];
    int b = blockIdx.y;
    for (int i = threadIdx.x; i < DD; i += 256) sv[i] = vec[(size_t)b * DD + i];
    __syncthreads();
    int d = blockIdx.x * 256 + threadIdx.x;
    const __half2* tp = (const __half2*)(t1 + (size_t)d * DD);
    float s = 0.f;
    #pragma unroll 4
    for (int i = 0; i < DD / 2; i++) {
        float2 a = __half22float2(tp[i]);
        s += a.x * sv[2 * i] + a.y * sv[2 * i + 1];
    }
    vb[(size_t)b * DD + d] = s + bias[d];
}

// ===== logits + half-cvt of inputs + per-(b,h) max via atomicMax =========
__global__ void k_logits(const float* __restrict__ inputs,
                         const float* __restrict__ W,
                         float* __restrict__ logits,
                         __half* __restrict__ inh,
                         int* __restrict__ maxi) {
    extern __shared__ float Wt[];   // [16][1024] + 16 ints tail
    int* smax = (int*)(Wt + DD * HH);
    int tid = threadIdx.x;
    if (tid < HH) smax[tid] = INT_MIN;
    for (int idx = tid; idx < DD * HH; idx += 256) {
        int i = idx >> 4, h = idx & 15;
        Wt[h * DD + i] = W[idx];
    }
    __syncthreads();
    int warp = tid >> 5, lane = tid & 31;
    float rowmax[HH];
    #pragma unroll
    for (int h = 0; h < HH; h++) rowmax[h] = -3.4e38f;
    for (int rr = 0; rr < 4; rr++) {
        int r = blockIdx.x * 32 + warp * 4 + rr;
        const float4* xp = (const float4*)(inputs + (size_t)r * DD);
        uint2* hp = (uint2*)(inh + (size_t)r * DD);
        float acc[HH];
        #pragma unroll
        for (int h = 0; h < HH; h++) acc[h] = 0.f;
        #pragma unroll
        for (int j = 0; j < 8; j++) {
            float4 x = xp[lane + 32 * j];
            hp[lane + 32 * j] = make_uint2(pack_h2(x.x, x.y), pack_h2(x.z, x.w));
            int i0 = (lane + 32 * j) * 4;
            #pragma unroll
            for (int h = 0; h < HH; h++) {
                float4 w = *(const float4*)&Wt[h * DD + i0];
                acc[h] += x.x * w.x + x.y * w.y + x.z * w.z + x.w * w.w;
            }
        }
        #pragma unroll
        for (int h = 0; h < HH; h++) {
            #pragma unroll
            for (int o = 16; o > 0; o >>= 1)
                acc[h] += __shfl_xor_sync(0xffffffffu, acc[h], o);
        }
        if (lane == 0) {
            #pragma unroll
            for (int h = 0; h < HH; h++) {
                logits[(size_t)r * HH + h] = acc[h];
                rowmax[h] = fmaxf(rowmax[h], acc[h]);
            }
        }
    }
    if (lane == 0) {
        #pragma unroll
        for (int h = 0; h < HH; h++) atomicMax(&smax[h], enc_f(rowmax[h]));
    }
    __syncthreads();
    if (tid < HH) {
        int b = (blockIdx.x * 32) >> 12;
        atomicMax(&maxi[b * HH + tid], smax[tid]);
    }
}

// ---------------- LayerNorm (in place over d_out rows) ------------------
__global__ void k_ln(float* __restrict__ X, const float* __restrict__ g,
                     const float* __restrict__ be) {
    int r = blockIdx.x;
    float* p = X + (size_t)r * DD;
    int i = threadIdx.x * 4;
    float4 x = *(const float4*)(p + i);
    __shared__ float red[256];
    float s = x.x + x.y + x.z + x.w;
    red[threadIdx.x] = s; __syncthreads();
    for (int o = 128; o > 0; o >>= 1) {
        if (threadIdx.x < o) red[threadIdx.x] += red[threadIdx.x + o];
        __syncthreads();
    }
    float mean = red[0] * (1.f / DD);
    __syncthreads();
    float d0 = x.x - mean, d1 = x.y - mean, d2 = x.z - mean, d3 = x.w - mean;
    red[threadIdx.x] = d0 * d0 + d1 * d1 + d2 * d2 + d3 * d3;
    __syncthreads();
    for (int o = 128; o > 0; o >>= 1) {
        if (threadIdx.x < o) red[threadIdx.x] += red[threadIdx.x + o];
        __syncthreads();
    }
    float inv = rsqrtf(red[0] * (1.f / DD) + 1e-6f);
    float4 o4;
    o4.x = d0 * inv * g[i + 0] + be[i + 0];
    o4.y = d1 * inv * g[i + 1] + be[i + 1];
    o4.z = d2 * inv * g[i + 2] + be[i + 2];
    o4.w = d3 * inv * g[i + 3] + be[i + 3];
    *(float4*)(p + i) = o4;
}

// ---------------- launcher ----------------------------------------------
extern "C" void kernel_launch(void* const* d_in, const int* in_sizes, int n_in,
                              void* d_out, int out_size) {
    (void)in_sizes; (void)n_in; (void)out_size;
    const float* inputs   = (const float*)d_in[0];
    const float* vector   = (const float*)d_in[1];
    const float* attw     = (const float*)d_in[2];
    const float* temp     = (const float*)d_in[3];
    const float* values   = (const float*)d_in[4];
    const float* oper     = (const float*)d_in[5];
    const float* ff1      = (const float*)d_in[6];
    const float* ff1_bias = (const float*)d_in[7];
    const float* ff2      = (const float*)d_in[8];
    const float* ff2_bias = (const float*)d_in[9];
    const float* ln_gamma = (const float*)d_in[10];
    const float* ln_beta  = (const float*)d_in[11];
    float* out = (float*)d_out;

    float *logit_p, *pref_p, *vb_p;
    int *maxi_p, *flag_p;
    __half *inh_p, *attnh_p, *h1h_p, *valT_p, *f1tT_p, *t1_p, *ff2T_p, *operh_p, *owT_p;
    cudaGetSymbolAddress((void**)&logit_p, g_logit);
    cudaGetSymbolAddress((void**)&maxi_p,  g_maxi);
    cudaGetSymbolAddress((void**)&flag_p,  g_flag);
    cudaGetSymbolAddress((void**)&pref_p,  g_pref);
    cudaGetSymbolAddress((void**)&vb_p,    g_vb);
    cudaGetSymbolAddress((void**)&inh_p,   g_in_h);
    cudaGetSymbolAddress((void**)&attnh_p, g_attn_h);
    cudaGetSymbolAddress((void**)&h1h_p,   g_h1h);
    cudaGetSymbolAddress((void**)&valT_p,  g_valTh);
    cudaGetSymbolAddress((void**)&f1tT_p,  g_f1tTh);
    cudaGetSymbolAddress((void**)&t1_p,    g_t1h);
    cudaGetSymbolAddress((void**)&ff2T_p,  g_ff2Th);
    cudaGetSymbolAddress((void**)&operh_p, g_operh);
    cudaGetSymbolAddress((void**)&owT_p,   g_owTh);

    cudaFuncSetAttribute(gemm_mma<2>, cudaFuncAttributeMaxDynamicSharedMemorySize, GEMM_SMEM);
    cudaFuncSetAttribute(gemm_mma<3>, cudaFuncAttributeMaxDynamicSharedMemorySize, GEMM_SMEM);
    cudaFuncSetAttribute(gemm_mma<5>, cudaFuncAttributeMaxDynamicSharedMemorySize, GEMM_SMEM);
    cudaFuncSetAttribute(k_logits, cudaFuncAttributeMaxDynamicSharedMemorySize, 65536 + 64);

    // 0: batched prep (4 transposes + oper cvt + maxi/flag reset)
    k_prep<<<dim3(32, 32, 5), dim3(32, 8)>>>(values, ff1, ff2, oper,
                                             valT_p, f1tT_p, t1_p, ff2T_p,
                                             operh_p, maxi_p, flag_p);
    // 1: logits + half inputs + per-(b,h) max
    k_logits<<<MR / 32, 256, 65536 + 64>>>(inputs, attw, logit_p, inh_p, maxi_p);
    // 2: vb = vector @ ff1_bot + b1
    k_vb<<<dim3(DD / 256, BB), 256>>>(vector, t1_p, ff1_bias, vb_p);
    // 3: fused v-GEMM + cumsum + att scaling; tail blocks (by>=128) do owT
    gemm_mma<5><<<dim3(8, MR / 128 + 8), 256, GEMM_SMEM>>>(
        inh_p, valT_p, t1_p, operh_p, attnh_p, pref_p, (const float*)owT_p,
        logit_p, maxi_p, temp, flag_p);
    // 4: h1 = relu(inputs@ff1_top + attn@OW + vb)  (half out)
    gemm_mma<2><<<dim3(8, MR / 128), 256, GEMM_SMEM>>>(inh_p, f1tT_p, attnh_p, owT_p,
                                                       h1h_p, nullptr, vb_p,
                                                       nullptr, nullptr, nullptr, nullptr);
    // 5: out = h1 @ ff2 + b2 + inputs (fp32)
    gemm_mma<3><<<dim3(8, MR / 128), 256, GEMM_SMEM>>>(h1h_p, ff2T_p, nullptr, nullptr,
                                                       out, (float*)inputs, ff2_bias,
                                                       nullptr, nullptr, nullptr, nullptr);
    // 6: LayerNorm in place
    k_ln<<<MR, 256>>>(out, ln_gamma, ln_beta);
}